// round 4
// baseline (speedup 1.0000x reference)
#include <cuda_runtime.h>
#include <math.h>

#define NB      8192
#define TILE_B  16
#define NT      256
#define SMEM_FLOATS 12464

__device__ __forceinline__ float silu_f(float x){
    return x * (1.0f / (1.0f + __expf(-x)));
}

// Warp-cooperative top-6 of 64 values (2 per lane). Tie-break: lower index.
__device__ __forceinline__ void topk6(float p0, float p1, int lane, int* sel, float* sv){
    #pragma unroll
    for (int t = 0; t < 6; ++t){
        float v = p0; int id = lane;
        if (p1 > v){ v = p1; id = lane + 32; }
        #pragma unroll
        for (int off = 16; off > 0; off >>= 1){
            float ov = __shfl_xor_sync(0xffffffffu, v, off);
            int  oid = __shfl_xor_sync(0xffffffffu, id, off);
            if (ov > v || (ov == v && oid < id)){ v = ov; id = oid; }
        }
        sv[t] = v; sel[t] = id;
        if (id == lane)           p0 = -INFINITY;
        else if (id == lane + 32) p1 = -INFINITY;
    }
}

// One row: gumbel perturb, top-5 select, one-hot write, exact-PL log-prob.
__device__ float row_topk_lp(const float* __restrict__ u,
                             const float* __restrict__ lg,
                             float m, float Z,
                             float* __restrict__ cfg,
                             int lane, int* selOut)
{
    float l0 = lg[lane], l1 = lg[lane + 32];
    float u0 = fmaxf(u[lane],      1e-10f);
    float u1 = fmaxf(u[lane + 32], 1e-10f);
    float p0 = l0 - __logf(-__logf(u0));
    float p1 = l1 - __logf(-__logf(u1));
    int sel[6]; float sv[6];
    topk6(p0, p1, lane, sel, sv);
    if (sv[4] - sv[5] < 1e-4f){
        p0 = l0 - (float)log(-log((double)u0));
        p1 = l1 - (float)log(-log((double)u1));
        topk6(p0, p1, lane, sel, sv);
    }
    float c0 = 0.f, c1 = 0.f;
    #pragma unroll
    for (int t = 0; t < 5; ++t){
        c0 += (sel[t] == lane)      ? 1.f : 0.f;
        c1 += (sel[t] == lane + 32) ? 1.f : 0.f;
    }
    cfg[lane]      = c0;
    cfg[lane + 32] = c1;

    // exact PL over 5! orderings via 2^5-subset DP
    float lsum = 0.f, e[5];
    #pragma unroll
    for (int t = 0; t < 5; ++t){
        float lt = lg[sel[t]];
        lsum += lt;
        e[t] = expf(lt - m);
    }
    float f[32];
    f[31] = 1.f;
    #pragma unroll
    for (int mask = 30; mask >= 0; --mask){
        float Em = 0.f, s = 0.f;
        #pragma unroll
        for (int t = 0; t < 5; ++t){
            if (mask & (1 << t)) Em += e[t];
            else                 s  += f[mask | (1 << t)];
        }
        f[mask] = __fdividef(s, Z - Em);
    }
    #pragma unroll
    for (int t = 0; t < 5; ++t) selOut[t] = sel[t];
    return lsum - 5.f * m + logf(f[0]);
}

__global__ __launch_bounds__(NT, 4)
void pcf_kernel(const float* __restrict__ Ua, const float* __restrict__ Ub,
                const float* __restrict__ AL,
                const float* __restrict__ W1, const float* __restrict__ b1,
                const float* __restrict__ W2, const float* __restrict__ b2,
                const float* __restrict__ V1, const float* __restrict__ c1,
                const float* __restrict__ V2, const float* __restrict__ c2,
                const float* __restrict__ V3, const float* __restrict__ c3,
                float* __restrict__ out)
{
    extern __shared__ float sm[];
    float* s_alog = sm;                    // 64
    float* s_scal = sm + 64;               // 4
    int*   s_sela = (int*)(sm + 68);       // 80 (16 rows x 5)
    float* s_lpa  = sm + 148;              // 16 -> pad to 176
    float* s_h    = sm + 176;              // 16x128 = 2048
    float* s_x    = s_h  + TILE_B * 128;   // 16x64  = 1024
    float* s_z1   = s_x  + TILE_B * 64;    // 16x256 = 4096
    float* s_z2   = s_z1 + TILE_B * 256;   // 16x256 = 4096
    float* s_blog = s_z2 + TILE_B * 256;   // 16x64  = 1024

    const int tid  = threadIdx.x;
    const int lane = tid & 31;
    const int wid  = tid >> 5;
    const int row0 = blockIdx.x * TILE_B;

    // --- alpha logits stats (block-constant) ---
    if (wid == 0){
        float l0 = AL[lane], l1 = AL[lane + 32];
        s_alog[lane] = l0; s_alog[lane + 32] = l1;
        float mv = fmaxf(l0, l1);
        #pragma unroll
        for (int off = 16; off > 0; off >>= 1)
            mv = fmaxf(mv, __shfl_xor_sync(0xffffffffu, mv, off));
        float zv = expf(l0 - mv) + expf(l1 - mv);
        #pragma unroll
        for (int off = 16; off > 0; off >>= 1)
            zv += __shfl_xor_sync(0xffffffffu, zv, off);
        if (lane == 0){ s_scal[0] = mv; s_scal[1] = zv; }
    }
    __syncthreads();
    const float ma = s_scal[0], Za = s_scal[1];

    // --- alpha selection + lp_a (8 warps, 16 rows -> 2 rows/warp) ---
    for (int rr = 0; rr < 2; ++rr){
        int r = wid * 2 + rr;
        int row = row0 + r;
        int sel[5];
        float lp = row_topk_lp(Ua + (size_t)row * 64, s_alog, ma, Za,
                               out + (size_t)row * 128, lane, sel);
        if (lane == 0){
            s_lpa[r] = lp;
            #pragma unroll
            for (int t = 0; t < 5; ++t) s_sela[r * 5 + t] = sel[t];
        }
    }
    __syncthreads();

    // --- h = silu(sum of 5 W1 rows + b1) ---
    for (int i = tid; i < TILE_B * 128; i += NT){
        int r = i >> 7, j = i & 127;
        float a = b1[j];
        #pragma unroll
        for (int t = 0; t < 5; ++t) a += W1[s_sela[r * 5 + t] * 128 + j];
        s_h[i] = silu_f(a);
    }
    __syncthreads();

    // --- ctx = h @ W2 + b2  (K=128, N=64): 4 row-groups x 64 cols ---
    {
        const int c = tid & 63, rg = tid >> 6;
        const float* Wp = W2 + c;
        float acc[4];
        #pragma unroll
        for (int i = 0; i < 4; i++) acc[i] = 0.f;
        for (int k = 0; k < 128; k += 4){
            float w0 = Wp[(k+0)*64], w1 = Wp[(k+1)*64];
            float w2v = Wp[(k+2)*64], w3 = Wp[(k+3)*64];
            #pragma unroll
            for (int i = 0; i < 4; i++){
                const float4 h4 = *reinterpret_cast<const float4*>(s_h + (rg*4 + i)*128 + k);
                acc[i] = fmaf(h4.x, w0, fmaf(h4.y, w1, fmaf(h4.z, w2v, fmaf(h4.w, w3, acc[i]))));
            }
        }
        float bb = b2[c];
        #pragma unroll
        for (int i = 0; i < 4; i++) s_x[(rg*4 + i)*64 + c] = acc[i] + bb;
    }
    __syncthreads();

    // --- z1 = silu(ctx @ V1[64:,:] + c1)  (K=64, N=256): col/thread, 16 rows ---
    {
        const int c = tid;
        const float* Vp = V1 + 64 * 256 + c;
        float acc[16];
        #pragma unroll
        for (int r = 0; r < 16; r++) acc[r] = 0.f;
        float v0 = Vp[0], v1 = Vp[256], v2v = Vp[512], v3 = Vp[768];
        for (int kb = 0; kb < 16; ++kb){
            float n0 = 0.f, n1 = 0.f, n2 = 0.f, n3 = 0.f;
            if (kb < 15){
                const float* q = Vp + (kb + 1) * 4 * 256;
                n0 = q[0]; n1 = q[256]; n2 = q[512]; n3 = q[768];
            }
            const int k = kb * 4;
            #pragma unroll
            for (int r = 0; r < 16; r++){
                const float4 x4 = *reinterpret_cast<const float4*>(s_x + r*64 + k);
                acc[r] = fmaf(x4.x, v0, fmaf(x4.y, v1, fmaf(x4.z, v2v, fmaf(x4.w, v3, acc[r]))));
            }
            v0 = n0; v1 = n1; v2v = n2; v3 = n3;
        }
        float bb = c1[c];
        #pragma unroll
        for (int r = 0; r < 16; r++) s_z1[r*256 + c] = silu_f(acc[r] + bb);
    }
    __syncthreads();

    // --- z2 = silu(z1 @ V2 + c2)  (K=256, N=256): col/thread, 16 rows ---
    {
        const int c = tid;
        const float* Vp = V2 + c;
        float acc[16];
        #pragma unroll
        for (int r = 0; r < 16; r++) acc[r] = 0.f;
        float v0 = Vp[0], v1 = Vp[256], v2v = Vp[512], v3 = Vp[768];
        for (int kb = 0; kb < 64; ++kb){
            float n0 = 0.f, n1 = 0.f, n2 = 0.f, n3 = 0.f;
            if (kb < 63){
                const float* q = Vp + (kb + 1) * 4 * 256;
                n0 = q[0]; n1 = q[256]; n2 = q[512]; n3 = q[768];
            }
            const int k = kb * 4;
            #pragma unroll
            for (int r = 0; r < 16; r++){
                const float4 z4 = *reinterpret_cast<const float4*>(s_z1 + r*256 + k);
                acc[r] = fmaf(z4.x, v0, fmaf(z4.y, v1, fmaf(z4.z, v2v, fmaf(z4.w, v3, acc[r]))));
            }
            v0 = n0; v1 = n1; v2v = n2; v3 = n3;
        }
        float bb = c2[c];
        #pragma unroll
        for (int r = 0; r < 16; r++) s_z2[r*256 + c] = silu_f(acc[r] + bb);
    }
    __syncthreads();

    // --- beta_logits = z2 @ V3 + c3  (K=256, N=64): 4 row-groups x 64 cols ---
    {
        const int c = tid & 63, rg = tid >> 6;
        const float* Vp = V3 + c;
        float acc[4];
        #pragma unroll
        for (int i = 0; i < 4; i++) acc[i] = 0.f;
        for (int k = 0; k < 256; k += 4){
            float v0 = Vp[(k+0)*64], v1 = Vp[(k+1)*64];
            float v2v = Vp[(k+2)*64], v3 = Vp[(k+3)*64];
            #pragma unroll
            for (int i = 0; i < 4; i++){
                const float4 z4 = *reinterpret_cast<const float4*>(s_z2 + (rg*4 + i)*256 + k);
                acc[i] = fmaf(z4.x, v0, fmaf(z4.y, v1, fmaf(z4.z, v2v, fmaf(z4.w, v3, acc[i]))));
            }
        }
        float bb = c3[c];
        #pragma unroll
        for (int i = 0; i < 4; i++) s_blog[(rg*4 + i)*64 + c] = acc[i] + bb;
    }
    __syncthreads();

    // --- beta selection + lp_b + final output ---
    for (int rr = 0; rr < 2; ++rr){
        int r = wid * 2 + rr;
        int row = row0 + r;
        const float* lg = s_blog + r * 64;
        float l0 = lg[lane], l1 = lg[lane + 32];
        float mv = fmaxf(l0, l1);
        #pragma unroll
        for (int off = 16; off > 0; off >>= 1)
            mv = fmaxf(mv, __shfl_xor_sync(0xffffffffu, mv, off));
        float zv = expf(l0 - mv) + expf(l1 - mv);
        #pragma unroll
        for (int off = 16; off > 0; off >>= 1)
            zv += __shfl_xor_sync(0xffffffffu, zv, off);
        int sel[5];
        float lpb = row_topk_lp(Ub + (size_t)row * 64, lg, mv, zv,
                                out + (size_t)row * 128 + 64, lane, sel);
        if (lane == 0)
            out[(size_t)NB * 128 + row] = s_lpa[r] + lpb;
    }
}

extern "C" void kernel_launch(void* const* d_in, const int* in_sizes, int n_in,
                              void* d_out, int out_size)
{
    (void)in_sizes; (void)n_in; (void)out_size;
    const float* Ua = (const float*)d_in[0];
    const float* Ub = (const float*)d_in[1];
    const float* AL = (const float*)d_in[2];
    const float* W1 = (const float*)d_in[3];
    const float* b1 = (const float*)d_in[4];
    const float* W2 = (const float*)d_in[5];
    const float* b2 = (const float*)d_in[6];
    const float* V1 = (const float*)d_in[7];
    const float* c1 = (const float*)d_in[8];
    const float* V2 = (const float*)d_in[9];
    const float* c2 = (const float*)d_in[10];
    const float* V3 = (const float*)d_in[11];
    const float* c3 = (const float*)d_in[12];
    float* out = (float*)d_out;

    const int smem_bytes = SMEM_FLOATS * (int)sizeof(float);
    cudaFuncSetAttribute(pcf_kernel, cudaFuncAttributeMaxDynamicSharedMemorySize, smem_bytes);
    pcf_kernel<<<NB / TILE_B, NT, smem_bytes>>>(Ua, Ub, AL, W1, b1, W2, b2,
                                                V1, c1, V2, c2, V3, c3, out);
}

// round 5
// speedup vs baseline: 1.8615x; 1.8615x over previous
#include <cuda_runtime.h>
#include <math.h>

#define NB      8192
#define TILE_B  32
#define NT      256
// header 272 | h@272(4096) x@4368(2048) z1@6416(8192) | z2@272 (aliases h,x) blog@8464 (inside dead z1)
#define OFF_H    272
#define OFF_X    4368
#define OFF_Z1   6416
#define OFF_Z2   272
#define OFF_BLOG 8464
#define SMEM_FLOATS 14608

__device__ __forceinline__ float silu_f(float x){
    return x * (1.0f / (1.0f + __expf(-x)));
}

// Warp-cooperative top-6 of 64 values (2 per lane). Tie-break: lower index.
__device__ __forceinline__ void topk6(float p0, float p1, int lane, int* sel, float* sv){
    #pragma unroll
    for (int t = 0; t < 6; ++t){
        float v = p0; int id = lane;
        if (p1 > v){ v = p1; id = lane + 32; }
        #pragma unroll
        for (int off = 16; off > 0; off >>= 1){
            float ov = __shfl_xor_sync(0xffffffffu, v, off);
            int  oid = __shfl_xor_sync(0xffffffffu, id, off);
            if (ov > v || (ov == v && oid < id)){ v = ov; id = oid; }
        }
        sv[t] = v; sel[t] = id;
        if (id == lane)           p0 = -INFINITY;
        else if (id == lane + 32) p1 = -INFINITY;
    }
}

// One row: gumbel perturb, top-5 select, one-hot write, exact-PL log-prob.
__device__ float row_topk_lp(const float* __restrict__ u,
                             const float* __restrict__ lg,
                             float m, float Z,
                             float* __restrict__ cfg,
                             int lane, int* selOut)
{
    float l0 = lg[lane], l1 = lg[lane + 32];
    float u0 = fmaxf(u[lane],      1e-10f);
    float u1 = fmaxf(u[lane + 32], 1e-10f);
    float p0 = l0 - __logf(-__logf(u0));
    float p1 = l1 - __logf(-__logf(u1));
    int sel[6]; float sv[6];
    topk6(p0, p1, lane, sel, sv);
    if (sv[4] - sv[5] < 1e-4f){
        p0 = l0 - (float)log(-log((double)u0));
        p1 = l1 - (float)log(-log((double)u1));
        topk6(p0, p1, lane, sel, sv);
    }
    float c0 = 0.f, c1 = 0.f;
    #pragma unroll
    for (int t = 0; t < 5; ++t){
        c0 += (sel[t] == lane)      ? 1.f : 0.f;
        c1 += (sel[t] == lane + 32) ? 1.f : 0.f;
    }
    cfg[lane]      = c0;
    cfg[lane + 32] = c1;

    // exact PL over 5! orderings via 2^5-subset DP
    float lsum = 0.f, e[5];
    #pragma unroll
    for (int t = 0; t < 5; ++t){
        float lt = lg[sel[t]];
        lsum += lt;
        e[t] = expf(lt - m);
    }
    float f[32];
    f[31] = 1.f;
    #pragma unroll
    for (int mask = 30; mask >= 0; --mask){
        float Em = 0.f, s = 0.f;
        #pragma unroll
        for (int t = 0; t < 5; ++t){
            if (mask & (1 << t)) Em += e[t];
            else                 s  += f[mask | (1 << t)];
        }
        f[mask] = __fdividef(s, Z - Em);
    }
    #pragma unroll
    for (int t = 0; t < 5; ++t) selOut[t] = sel[t];
    return lsum - 5.f * m + logf(f[0]);
}

__global__ __launch_bounds__(NT, 3)
void pcf_kernel(const float* __restrict__ Ua, const float* __restrict__ Ub,
                const float* __restrict__ AL,
                const float* __restrict__ W1, const float* __restrict__ b1,
                const float* __restrict__ W2, const float* __restrict__ b2,
                const float* __restrict__ V1, const float* __restrict__ c1,
                const float* __restrict__ V2, const float* __restrict__ c2,
                const float* __restrict__ V3, const float* __restrict__ c3,
                float* __restrict__ out)
{
    extern __shared__ float sm[];
    float* s_alog = sm;                    // 64
    float* s_scal = sm + 64;               // 4
    int*   s_sela = (int*)(sm + 68);       // 160
    float* s_lpa  = sm + 228;              // 32 -> header ends 272
    float* s_h    = sm + OFF_H;
    float* s_x    = sm + OFF_X;
    float* s_z1   = sm + OFF_Z1;
    float* s_z2   = sm + OFF_Z2;           // aliases h,x (dead by then)
    float* s_blog = sm + OFF_BLOG;         // inside dead z1

    const int tid  = threadIdx.x;
    const int lane = tid & 31;
    const int wid  = tid >> 5;
    const int row0 = blockIdx.x * TILE_B;

    // --- alpha logits stats (block-constant) ---
    if (wid == 0){
        float l0 = AL[lane], l1 = AL[lane + 32];
        s_alog[lane] = l0; s_alog[lane + 32] = l1;
        float mv = fmaxf(l0, l1);
        #pragma unroll
        for (int off = 16; off > 0; off >>= 1)
            mv = fmaxf(mv, __shfl_xor_sync(0xffffffffu, mv, off));
        float zv = expf(l0 - mv) + expf(l1 - mv);
        #pragma unroll
        for (int off = 16; off > 0; off >>= 1)
            zv += __shfl_xor_sync(0xffffffffu, zv, off);
        if (lane == 0){ s_scal[0] = mv; s_scal[1] = zv; }
    }
    __syncthreads();
    const float ma = s_scal[0], Za = s_scal[1];

    // --- alpha selection + lp_a (4 rows per warp) ---
    for (int rr = 0; rr < 4; ++rr){
        int r = wid * 4 + rr;
        int row = row0 + r;
        int sel[5];
        float lp = row_topk_lp(Ua + (size_t)row * 64, s_alog, ma, Za,
                               out + (size_t)row * 128, lane, sel);
        if (lane == 0){
            s_lpa[r] = lp;
            #pragma unroll
            for (int t = 0; t < 5; ++t) s_sela[r * 5 + t] = sel[t];
        }
    }
    __syncthreads();

    // --- h = silu(sum of 5 W1 rows + b1) ---
    for (int i = tid; i < TILE_B * 128; i += NT){
        int r = i >> 7, j = i & 127;
        float a = b1[j];
        #pragma unroll
        for (int t = 0; t < 5; ++t) a += W1[s_sela[r * 5 + t] * 128 + j];
        s_h[i] = silu_f(a);
    }
    __syncthreads();

    // --- ctx = h @ W2 + b2  (K=128, N=64): 4 cols x 2 rows per thread ---
    {
        const int cg = tid & 15, rg = tid >> 4;   // 16 col-groups, 16 row-groups x 2 rows
        const float* Wp = W2 + 4 * cg;
        float acc[2][4];
        #pragma unroll
        for (int r = 0; r < 2; r++)
            #pragma unroll
            for (int c = 0; c < 4; c++) acc[r][c] = 0.f;
        for (int k = 0; k < 128; k += 4){
            float4 w0 = *(const float4*)(Wp + (k+0)*64);
            float4 w1 = *(const float4*)(Wp + (k+1)*64);
            float4 w2v = *(const float4*)(Wp + (k+2)*64);
            float4 w3 = *(const float4*)(Wp + (k+3)*64);
            #pragma unroll
            for (int r = 0; r < 2; r++){
                const float4 h4 = *(const float4*)(s_h + (rg*2 + r)*128 + k);
                acc[r][0] = fmaf(h4.x, w0.x, fmaf(h4.y, w1.x, fmaf(h4.z, w2v.x, fmaf(h4.w, w3.x, acc[r][0]))));
                acc[r][1] = fmaf(h4.x, w0.y, fmaf(h4.y, w1.y, fmaf(h4.z, w2v.y, fmaf(h4.w, w3.y, acc[r][1]))));
                acc[r][2] = fmaf(h4.x, w0.z, fmaf(h4.y, w1.z, fmaf(h4.z, w2v.z, fmaf(h4.w, w3.z, acc[r][2]))));
                acc[r][3] = fmaf(h4.x, w0.w, fmaf(h4.y, w1.w, fmaf(h4.z, w2v.w, fmaf(h4.w, w3.w, acc[r][3]))));
            }
        }
        float4 bb = *(const float4*)(b2 + 4*cg);
        #pragma unroll
        for (int r = 0; r < 2; r++){
            float4 o = make_float4(acc[r][0]+bb.x, acc[r][1]+bb.y, acc[r][2]+bb.z, acc[r][3]+bb.w);
            *(float4*)(s_x + (rg*2 + r)*64 + 4*cg) = o;
        }
    }
    __syncthreads();

    // --- z1 = silu(ctx @ V1[64:,:] + c1)  (K=64, N=256): 4 cols x 8 rows ---
    {
        const int cg = tid & 63, rg = tid >> 6;   // 64 col-groups, 4 row-groups x 8 rows
        const float* Vp = V1 + 64 * 256 + 4 * cg;
        float acc[8][4];
        #pragma unroll
        for (int r = 0; r < 8; r++)
            #pragma unroll
            for (int c = 0; c < 4; c++) acc[r][c] = 0.f;
        for (int k = 0; k < 64; k += 4){
            float4 w0 = *(const float4*)(Vp + (k+0)*256);
            float4 w1 = *(const float4*)(Vp + (k+1)*256);
            float4 w2v = *(const float4*)(Vp + (k+2)*256);
            float4 w3 = *(const float4*)(Vp + (k+3)*256);
            #pragma unroll
            for (int r = 0; r < 8; r++){
                const float4 x4 = *(const float4*)(s_x + (rg*8 + r)*64 + k);
                acc[r][0] = fmaf(x4.x, w0.x, fmaf(x4.y, w1.x, fmaf(x4.z, w2v.x, fmaf(x4.w, w3.x, acc[r][0]))));
                acc[r][1] = fmaf(x4.x, w0.y, fmaf(x4.y, w1.y, fmaf(x4.z, w2v.y, fmaf(x4.w, w3.y, acc[r][1]))));
                acc[r][2] = fmaf(x4.x, w0.z, fmaf(x4.y, w1.z, fmaf(x4.z, w2v.z, fmaf(x4.w, w3.z, acc[r][2]))));
                acc[r][3] = fmaf(x4.x, w0.w, fmaf(x4.y, w1.w, fmaf(x4.z, w2v.w, fmaf(x4.w, w3.w, acc[r][3]))));
            }
        }
        float4 bb = *(const float4*)(c1 + 4*cg);
        #pragma unroll
        for (int r = 0; r < 8; r++){
            float4 o = make_float4(silu_f(acc[r][0]+bb.x), silu_f(acc[r][1]+bb.y),
                                   silu_f(acc[r][2]+bb.z), silu_f(acc[r][3]+bb.w));
            *(float4*)(s_z1 + (rg*8 + r)*256 + 4*cg) = o;
        }
    }
    __syncthreads();

    // --- z2 = silu(z1 @ V2 + c2)  (K=256, N=256): 4 cols x 8 rows ---
    {
        const int cg = tid & 63, rg = tid >> 6;
        const float* Vp = V2 + 4 * cg;
        float acc[8][4];
        #pragma unroll
        for (int r = 0; r < 8; r++)
            #pragma unroll
            for (int c = 0; c < 4; c++) acc[r][c] = 0.f;
        for (int k = 0; k < 256; k += 4){
            float4 w0 = *(const float4*)(Vp + (k+0)*256);
            float4 w1 = *(const float4*)(Vp + (k+1)*256);
            float4 w2v = *(const float4*)(Vp + (k+2)*256);
            float4 w3 = *(const float4*)(Vp + (k+3)*256);
            #pragma unroll
            for (int r = 0; r < 8; r++){
                const float4 z4 = *(const float4*)(s_z1 + (rg*8 + r)*256 + k);
                acc[r][0] = fmaf(z4.x, w0.x, fmaf(z4.y, w1.x, fmaf(z4.z, w2v.x, fmaf(z4.w, w3.x, acc[r][0]))));
                acc[r][1] = fmaf(z4.x, w0.y, fmaf(z4.y, w1.y, fmaf(z4.z, w2v.y, fmaf(z4.w, w3.y, acc[r][1]))));
                acc[r][2] = fmaf(z4.x, w0.z, fmaf(z4.y, w1.z, fmaf(z4.z, w2v.z, fmaf(z4.w, w3.z, acc[r][2]))));
                acc[r][3] = fmaf(z4.x, w0.w, fmaf(z4.y, w1.w, fmaf(z4.z, w2v.w, fmaf(z4.w, w3.w, acc[r][3]))));
            }
        }
        float4 bb = *(const float4*)(c2 + 4*cg);
        #pragma unroll
        for (int r = 0; r < 8; r++){
            float4 o = make_float4(silu_f(acc[r][0]+bb.x), silu_f(acc[r][1]+bb.y),
                                   silu_f(acc[r][2]+bb.z), silu_f(acc[r][3]+bb.w));
            *(float4*)(s_z2 + (rg*8 + r)*256 + 4*cg) = o;
        }
    }
    __syncthreads();

    // --- beta_logits = z2 @ V3 + c3  (K=256, N=64): 4 cols x 2 rows ---
    {
        const int cg = tid & 15, rg = tid >> 4;
        const float* Vp = V3 + 4 * cg;
        float acc[2][4];
        #pragma unroll
        for (int r = 0; r < 2; r++)
            #pragma unroll
            for (int c = 0; c < 4; c++) acc[r][c] = 0.f;
        for (int k = 0; k < 256; k += 4){
            float4 w0 = *(const float4*)(Vp + (k+0)*64);
            float4 w1 = *(const float4*)(Vp + (k+1)*64);
            float4 w2v = *(const float4*)(Vp + (k+2)*64);
            float4 w3 = *(const float4*)(Vp + (k+3)*64);
            #pragma unroll
            for (int r = 0; r < 2; r++){
                const float4 z4 = *(const float4*)(s_z2 + (rg*2 + r)*256 + k);
                acc[r][0] = fmaf(z4.x, w0.x, fmaf(z4.y, w1.x, fmaf(z4.z, w2v.x, fmaf(z4.w, w3.x, acc[r][0]))));
                acc[r][1] = fmaf(z4.x, w0.y, fmaf(z4.y, w1.y, fmaf(z4.z, w2v.y, fmaf(z4.w, w3.y, acc[r][1]))));
                acc[r][2] = fmaf(z4.x, w0.z, fmaf(z4.y, w1.z, fmaf(z4.z, w2v.z, fmaf(z4.w, w3.z, acc[r][2]))));
                acc[r][3] = fmaf(z4.x, w0.w, fmaf(z4.y, w1.w, fmaf(z4.z, w2v.w, fmaf(z4.w, w3.w, acc[r][3]))));
            }
        }
        float4 bb = *(const float4*)(c3 + 4*cg);
        #pragma unroll
        for (int r = 0; r < 2; r++){
            float4 o = make_float4(acc[r][0]+bb.x, acc[r][1]+bb.y, acc[r][2]+bb.z, acc[r][3]+bb.w);
            *(float4*)(s_blog + (rg*2 + r)*64 + 4*cg) = o;
        }
    }
    __syncthreads();

    // --- beta selection + lp_b + final output ---
    for (int rr = 0; rr < 4; ++rr){
        int r = wid * 4 + rr;
        int row = row0 + r;
        const float* lg = s_blog + r * 64;
        float l0 = lg[lane], l1 = lg[lane + 32];
        float mv = fmaxf(l0, l1);
        #pragma unroll
        for (int off = 16; off > 0; off >>= 1)
            mv = fmaxf(mv, __shfl_xor_sync(0xffffffffu, mv, off));
        float zv = expf(l0 - mv) + expf(l1 - mv);
        #pragma unroll
        for (int off = 16; off > 0; off >>= 1)
            zv += __shfl_xor_sync(0xffffffffu, zv, off);
        int sel[5];
        float lpb = row_topk_lp(Ub + (size_t)row * 64, lg, mv, zv,
                                out + (size_t)row * 128 + 64, lane, sel);
        if (lane == 0)
            out[(size_t)NB * 128 + row] = s_lpa[r] + lpb;
    }
}

extern "C" void kernel_launch(void* const* d_in, const int* in_sizes, int n_in,
                              void* d_out, int out_size)
{
    (void)in_sizes; (void)n_in; (void)out_size;
    const float* Ua = (const float*)d_in[0];
    const float* Ub = (const float*)d_in[1];
    const float* AL = (const float*)d_in[2];
    const float* W1 = (const float*)d_in[3];
    const float* b1 = (const float*)d_in[4];
    const float* W2 = (const float*)d_in[5];
    const float* b2 = (const float*)d_in[6];
    const float* V1 = (const float*)d_in[7];
    const float* c1 = (const float*)d_in[8];
    const float* V2 = (const float*)d_in[9];
    const float* c2 = (const float*)d_in[10];
    const float* V3 = (const float*)d_in[11];
    const float* c3 = (const float*)d_in[12];
    float* out = (float*)d_out;

    const int smem_bytes = SMEM_FLOATS * (int)sizeof(float);
    cudaFuncSetAttribute(pcf_kernel, cudaFuncAttributeMaxDynamicSharedMemorySize, smem_bytes);
    pcf_kernel<<<NB / TILE_B, NT, smem_bytes>>>(Ua, Ub, AL, W1, b1, W2, b2,
                                                V1, c1, V2, c2, V3, c3, out);
}